// round 14
// baseline (speedup 1.0000x reference)
#include <cuda_runtime.h>
#include <cstdint>

// Fixed problem shape: Q=4096, N=65536, D=128, K_TOP=21.
#define D_DIM 128
#define K_TOP 21
#define TILE_N 128         // n-tile per CTA
#define TILE_Q 256         // q-tile per CTA (2 q-halves of 128)
#define KCH   32           // xq k-chunk per cp.async stage
#define NSTAGE 3           // cp.async ring depth
#define SA_STRIDE 260      // [k][q] row stride (floats), 16B-aligned rows
#define SB_STRIDE 132
#define SB_WORDS (D_DIM * SB_STRIDE)
#define SA_WORDS (KCH * SA_STRIDE)
#define NTHREADS 1024

// Monotonic map fp32 -> u32 (order-preserving, total order).
__device__ __forceinline__ unsigned fp32_ord(float f) {
    unsigned u = __float_as_uint(f);
    return u ^ (((int)u >> 31) | 0x80000000u);
}

// Packed dual-fp32 FMA: per-lane .rn — bit-identical to two scalar fmaf's.
__device__ __forceinline__ unsigned long long ffma2(
    unsigned long long a, unsigned long long b, unsigned long long c)
{
    unsigned long long d;
    asm("fma.rn.f32x2 %0, %1, %2, %3;" : "=l"(d) : "l"(a), "l"(b), "l"(c));
    return d;
}

__device__ __forceinline__ unsigned long long dup_f32(float x)
{
    unsigned long long d;
    asm("mov.b64 %0, {%1, %1};" : "=l"(d) : "r"(__float_as_uint(x)));
    return d;
}

// Async-copy one 32k x 256q chunk of xq, transposed, into dstbuf[k][q].
// lane -> k (128B-coalesced global), f>>5 -> q.
__device__ __forceinline__ void load_chunk_async(
    float* dstbuf, const float* __restrict__ xq, int q0, int kc, int tid)
{
#pragma unroll
    for (int i = 0; i < 8; i++) {
        int f  = i * NTHREADS + tid;     // 0..8191
        int kl = f & 31;                 // k within chunk (= lane)
        int q  = f >> 5;                 // q within tile 0..255
        const float* g = xq + (size_t)(q0 + q) * D_DIM + kc + kl;
        unsigned saddr = (unsigned)__cvta_generic_to_shared(dstbuf + kl * SA_STRIDE + q);
        asm volatile("cp.async.ca.shared.global [%0], [%1], 4;\n" :: "r"(saddr), "l"(g));
    }
    asm volatile("cp.async.commit_group;\n" ::: "memory");
}

// ---------------------------------------------------------------------------
// Fused GEMM + top-21. CTA owns 128 database rows (xb resident in smem);
// xq streams in 256-q tiles through a 3-stage cp.async ring of 32-k chunks.
// 1024 threads: warp w = row-group (w&15, 8 rows) x q-half (w>>4, 128 q).
// Microtile 8n x 4q/lane via packed fma.rn.f32x2, pairs along n (b comes
// pre-packed from smem; a loaded as one LDS.128 @16B lane stride + dups —
// the exact R9 idiom). Each q-half keeps its own top-21 per row; merged at
// emit (keys unique). Accumulation: single fp32 acc per (n,q), k ascending —
// bit-identical to scalar; do not change.
// ---------------------------------------------------------------------------
__global__ __launch_bounds__(NTHREADS, 1) void fused_gemm_topk_kernel(
    const float* __restrict__ xq,   // [Q, 128]
    const float* __restrict__ xb,   // [N, 128]
    int Q, int N, float* __restrict__ out)   // out [21, N] (float-encoded idx)
{
    extern __shared__ float smem[];
    float* sB = smem;                        // [128][132]  xb^T (k-major)
    float* sA = smem + SB_WORDS;             // [3][32][260] xq ring
    unsigned long long* lists = (unsigned long long*)(sA + NSTAGE * SA_WORDS); // [2][128][21]
    unsigned* thresh = (unsigned*)(lists + 2 * TILE_N * K_TOP);                // [2][128]

    const int tid = threadIdx.x;
    const int tx  = tid & 31;        // lane: 4 consecutive q per thread
    const int ty  = tid >> 5;        // warp id
    const int rb  = (ty & 15) * 8;   // row base (8 rows)
    const int qh  = ty >> 4;         // q-half (0/1): q offset qh*128
    const int n0  = blockIdx.x * TILE_N;

    // Init top-k state (key 0 can't collide with any real key).
    for (int i = tid; i < 2 * TILE_N * K_TOP; i += NTHREADS) lists[i] = 0ull;
    for (int i = tid; i < 2 * TILE_N; i += NTHREADS) thresh[i] = 0u;

    // Load this CTA's xb tile once, transposed: sB[k][n].
#pragma unroll
    for (int i = 0; i < 4; i++) {
        int idx = i * NTHREADS + tid;     // 0..4095 float4s
        int r   = idx >> 5;               // n row
        int c4  = (idx & 31) << 2;        // k 0,4,...,124
        float4 b = *(const float4*)(xb + (size_t)(n0 + r) * D_DIM + c4);
        sB[(c4 + 0) * SB_STRIDE + r] = b.x;
        sB[(c4 + 1) * SB_STRIDE + r] = b.y;
        sB[(c4 + 2) * SB_STRIDE + r] = b.z;
        sB[(c4 + 3) * SB_STRIDE + r] = b.w;
    }

    const int nTiles = Q / TILE_Q;               // 16
    const int cTotal = nTiles * (D_DIM / KCH);   // 64

    // Prologue: chunks 0 and 1 in flight.
    load_chunk_async(sA,            xq, 0, 0,   tid);
    load_chunk_async(sA + SA_WORDS, xq, 0, KCH, tid);

    int ct = 0;
    for (int tile = 0; tile < nTiles; tile++) {
        const int q0 = tile * TILE_Q + qh * 128;

        // acc2[p][j]: packed pair (row rb+2p, rb+2p+1), q = q0 + tx*4 + j.
        unsigned long long acc2[4][4];
#pragma unroll
        for (int p = 0; p < 4; p++)
#pragma unroll
            for (int j = 0; j < 4; j++) acc2[p][j] = 0ull;

        for (int c = 0; c < D_DIM / KCH; c++, ct++) {
            // Wait for chunk ct (pending groups: ct .. ct+1).
            if (ct == cTotal - 1) {
                asm volatile("cp.async.wait_group 0;\n" ::: "memory");
            } else {
                asm volatile("cp.async.wait_group 1;\n" ::: "memory");
            }
            // Single barrier: publishes chunk ct AND closes reads of the
            // buffer chunk ct+2 will overwrite.
            __syncthreads();

            if (ct + 2 < cTotal) {
                int nct = ct + 2;
                load_chunk_async(sA + (nct % NSTAGE) * SA_WORDS, xq,
                                 (nct >> 2) * TILE_Q, (nct & 3) * KCH, tid);
            }

            const float* A  = sA + (ct % NSTAGE) * SA_WORDS + qh * 128 + tx * 4;
            const float* Bc = sB + c * KCH * SB_STRIDE + rb;
#pragma unroll 8
            for (int k = 0; k < KCH; k++) {
                // b: warp-uniform 2x16B -> broadcast; 4 pre-packed n-pairs.
                const float* Bk = Bc + k * SB_STRIDE;
                ulonglong2 b01 = *(const ulonglong2*)(Bk);
                ulonglong2 b23 = *(const ulonglong2*)(Bk + 4);
                // a: conflict-free LDS.128 (16B lane stride, 512B span).
                float4 av = *(const float4*)(A + k * SA_STRIDE);
                unsigned long long a0 = dup_f32(av.x);
                unsigned long long a1 = dup_f32(av.y);
                unsigned long long a2 = dup_f32(av.z);
                unsigned long long a3 = dup_f32(av.w);
                acc2[0][0] = ffma2(b01.x, a0, acc2[0][0]);
                acc2[1][0] = ffma2(b01.y, a0, acc2[1][0]);
                acc2[2][0] = ffma2(b23.x, a0, acc2[2][0]);
                acc2[3][0] = ffma2(b23.y, a0, acc2[3][0]);
                acc2[0][1] = ffma2(b01.x, a1, acc2[0][1]);
                acc2[1][1] = ffma2(b01.y, a1, acc2[1][1]);
                acc2[2][1] = ffma2(b23.x, a1, acc2[2][1]);
                acc2[3][1] = ffma2(b23.y, a1, acc2[3][1]);
                acc2[0][2] = ffma2(b01.x, a2, acc2[0][2]);
                acc2[1][2] = ffma2(b01.y, a2, acc2[1][2]);
                acc2[2][2] = ffma2(b23.x, a2, acc2[2][2]);
                acc2[3][2] = ffma2(b23.y, a2, acc2[3][2]);
                acc2[0][3] = ffma2(b01.x, a3, acc2[0][3]);
                acc2[1][3] = ffma2(b01.y, a3, acc2[1][3]);
                acc2[2][3] = ffma2(b23.x, a3, acc2[2][3]);
                acc2[3][3] = ffma2(b23.y, a3, acc2[3][3]);
            }
        }

        // ---------------- Top-k update (per q-half, warp-private rows) -----
        // Warp owns rows rb..rb+7 in half qh. Pair p: lo -> row rb+2p,
        // hi -> row rb+2p+1; lane tx holds q = q0 + tx*4 + j.
        unsigned long long* Lh = lists + (size_t)qh * TILE_N * K_TOP;
        unsigned* Th = thresh + qh * TILE_N;
#pragma unroll
        for (int p = 0; p < 4; p++) {
#pragma unroll
            for (int half = 0; half < 2; half++) {
                int row = rb + 2 * p + half;
                unsigned th = Th[row];
                unsigned ov[4];
                bool any = false;
#pragma unroll
                for (int j = 0; j < 4; j++) {
                    unsigned bits = half ? (unsigned)(acc2[p][j] >> 32)
                                         : (unsigned)(acc2[p][j] & 0xFFFFFFFFull);
                    ov[j] = fp32_ord(__uint_as_float(bits));
                    any |= (ov[j] >= th);
                }
                unsigned bal = __ballot_sync(0xffffffffu, any);
                while (bal) {
                    int t = __ffs(bal) - 1;
                    bal &= bal - 1;
                    if (tx == t) {
                        unsigned long long* L = Lh + (size_t)row * K_TOP;
#pragma unroll
                        for (int j = 0; j < 4; j++) {
                            unsigned long long key =
                                ((unsigned long long)ov[j] << 32) |
                                (unsigned long long)(0xFFFFFFFFu - (unsigned)(q0 + tx * 4 + j));
                            if (key > L[K_TOP - 1]) {
                                int pp = K_TOP - 1;
                                while (pp > 0 && L[pp - 1] < key) { L[pp] = L[pp - 1]; pp--; }
                                L[pp] = key;
                            }
                        }
                        Th[row] = (unsigned)(L[K_TOP - 1] >> 32);
                    }
                    __syncwarp();
                }
            }
        }
        // lists/thresh writes close at the next chunk's __syncthreads (or the
        // one below after the last tile).
    }

    __syncthreads();
    // Emit: merge the two q-half lists per row (two-pointer over sorted
    // descending key lists; keys globally unique), write top-21 indices as
    // FLOAT32 values (0..4095 exactly representable).
    if (tid < TILE_N) {
        int row = tid;
        const unsigned long long* L0 = lists + (size_t)row * K_TOP;
        const unsigned long long* L1 = lists + (size_t)(TILE_N + row) * K_TOP;
        int i0 = 0, i1 = 0;
#pragma unroll
        for (int k = 0; k < K_TOP; k++) {
            unsigned long long k0 = L0[i0], k1 = L1[i1];
            unsigned long long m;
            if (k0 > k1) { m = k0; i0++; } else { m = k1; i1++; }
            unsigned idx = 0xFFFFFFFFu - (unsigned)(m & 0xFFFFFFFFull);
            out[(size_t)k * N + (n0 + row)] = (float)idx;
        }
    }
}

// ---------------------------------------------------------------------------
// Launch. Inputs bound BY SIZE: N comes from out_size (out is [21, N]); the
// input with N*128 elements is xb (database), the other is xq (queries).
// ---------------------------------------------------------------------------
extern "C" void kernel_launch(void* const* d_in, const int* in_sizes, int n_in,
                              void* d_out, int out_size)
{
    float* out = (float*)d_out;

    const int N = out_size / K_TOP;
    const float* xq;
    const float* xb;
    int Q;

    if (in_sizes[0] == N * D_DIM && in_sizes[1] != N * D_DIM) {
        xb = (const float*)d_in[0];
        xq = (const float*)d_in[1];
        Q  = in_sizes[1] / D_DIM;
    } else {
        xq = (const float*)d_in[0];
        xb = (const float*)d_in[1];
        Q  = in_sizes[0] / D_DIM;
    }

    const int smem_bytes = SB_WORDS * 4 + NSTAGE * SA_WORDS * 4
                         + 2 * TILE_N * K_TOP * 8 + 2 * TILE_N * 4;   // ~207 KB
    cudaFuncSetAttribute(fused_gemm_topk_kernel,
                         cudaFuncAttributeMaxDynamicSharedMemorySize, smem_bytes);

    fused_gemm_topk_kernel<<<N / TILE_N, NTHREADS, smem_bytes>>>(xq, xb, Q, N, out);
}

// round 15
// speedup vs baseline: 1.4227x; 1.4227x over previous
#include <cuda_runtime.h>
#include <cstdint>

// Fixed problem shape: Q=4096, N=65536, D=128, K_TOP=21.
#define D_DIM 128
#define K_TOP 21
#define TILE  64           // n-tile per CTA (2 CTAs co-resident per SM)
#define QTILE 128          // q-tile
#define KCH   32           // xq k-chunk per cp.async stage
#define NSTAGE 3           // cp.async ring depth
#define SA_STRIDE 132      // padded row stride (floats), 16B-aligned rows
#define SB_STRIDE 132
#define SB_WORDS (TILE * SB_STRIDE * 2)   // [128 k][66..] -> see layout below
#define NTHREADS 512

// sB layout: [k][n] with n = 0..63, stride 68 floats (16B-aligned, padded).
#define SBN_STRIDE 68
#define SB_TOT (D_DIM * SBN_STRIDE)
#define SA_WORDS (KCH * SA_STRIDE)

// Monotonic map fp32 -> u32 (order-preserving, total order).
__device__ __forceinline__ unsigned fp32_ord(float f) {
    unsigned u = __float_as_uint(f);
    return u ^ (((int)u >> 31) | 0x80000000u);
}

// Packed dual-fp32 FMA: per-lane .rn — bit-identical to two scalar fmaf's.
__device__ __forceinline__ unsigned long long ffma2(
    unsigned long long a, unsigned long long b, unsigned long long c)
{
    unsigned long long d;
    asm("fma.rn.f32x2 %0, %1, %2, %3;" : "=l"(d) : "l"(a), "l"(b), "l"(c));
    return d;
}

__device__ __forceinline__ unsigned long long dup_f32(float x)
{
    unsigned long long d;
    asm("mov.b64 %0, {%1, %1};" : "=l"(d) : "r"(__float_as_uint(x)));
    return d;
}

// Async-copy one 32k x 128q chunk of xq, transposed, into dstbuf[k][q].
// lane -> k (128B-coalesced global), f>>5 -> q.
__device__ __forceinline__ void load_chunk_async(
    float* dstbuf, const float* __restrict__ xq, int q0, int kc, int tid)
{
#pragma unroll
    for (int i = 0; i < 8; i++) {
        int f  = i * NTHREADS + tid;     // 0..4095
        int kl = f & 31;                 // k within chunk (= lane)
        int q  = f >> 5;                 // q within tile
        const float* g = xq + (size_t)(q0 + q) * D_DIM + kc + kl;
        unsigned saddr = (unsigned)__cvta_generic_to_shared(dstbuf + kl * SA_STRIDE + q);
        asm volatile("cp.async.ca.shared.global [%0], [%1], 4;\n" :: "r"(saddr), "l"(g));
    }
    asm volatile("cp.async.commit_group;\n" ::: "memory");
}

// ---------------------------------------------------------------------------
// Fused GEMM + top-21. CTA owns 64 database rows (xb resident in smem);
// xq streams through a 3-stage cp.async ring. 512 threads (16 warps), 2 CTAs
// co-resident per SM (8 warps/SMSP total). Warp = 4 n-rows x 128 q,
// 4q/lane, packed fma.rn.f32x2 pairs along n (b pre-packed from smem) —
// the proven R9 microtile. Accumulation: single fp32 acc per (n,q), k
// ascending — bit-identical to scalar; do not change.
// ---------------------------------------------------------------------------
__global__ __launch_bounds__(NTHREADS, 2) void fused_gemm_topk_kernel(
    const float* __restrict__ xq,   // [Q, 128]
    const float* __restrict__ xb,   // [N, 128]
    int Q, int N, float* __restrict__ out)   // out [21, N] (float-encoded idx)
{
    extern __shared__ float smem[];
    float* sB = smem;                        // [128][68]  xb^T (k-major, 64 n)
    float* sA = smem + SB_TOT;               // [3][32][132] xq ring
    unsigned long long* lists = (unsigned long long*)(sA + NSTAGE * SA_WORDS); // [64][21]
    unsigned* thresh = (unsigned*)(lists + TILE * K_TOP);                      // [64]

    const int tid = threadIdx.x;
    const int tx  = tid & 31;        // lane: 4 consecutive q per thread
    const int ty  = tid >> 5;        // warp id: 4 n-rows (2 n-pairs)
    const int n0  = blockIdx.x * TILE;

    // Init top-k state (key 0 can't collide with any real key).
    for (int i = tid; i < TILE * K_TOP; i += NTHREADS) lists[i] = 0ull;
    for (int i = tid; i < TILE; i += NTHREADS) thresh[i] = 0u;

    // Load this CTA's xb tile once, transposed: sB[k][n] (64 rows).
#pragma unroll
    for (int i = 0; i < 4; i++) {
        int idx = i * NTHREADS + tid;     // 0..2047 float4s
        int r   = idx >> 5;               // n row 0..63
        int c4  = (idx & 31) << 2;        // k 0,4,...,124
        float4 b = *(const float4*)(xb + (size_t)(n0 + r) * D_DIM + c4);
        sB[(c4 + 0) * SBN_STRIDE + r] = b.x;
        sB[(c4 + 1) * SBN_STRIDE + r] = b.y;
        sB[(c4 + 2) * SBN_STRIDE + r] = b.z;
        sB[(c4 + 3) * SBN_STRIDE + r] = b.w;
    }

    const int nTiles = Q / QTILE;                // 32
    const int cTotal = nTiles * (D_DIM / KCH);   // 128

    // Prologue: chunks 0 and 1 in flight.
    load_chunk_async(sA,            xq, 0, 0,   tid);
    load_chunk_async(sA + SA_WORDS, xq, 0, KCH, tid);

    int ct = 0;
    for (int tile = 0; tile < nTiles; tile++) {
        const int q0 = tile * QTILE;

        // acc2[p][j]: packed pair (row ty*4+2p, ty*4+2p+1), q = q0 + tx*4 + j.
        unsigned long long acc2[2][4];
#pragma unroll
        for (int p = 0; p < 2; p++)
#pragma unroll
            for (int j = 0; j < 4; j++) acc2[p][j] = 0ull;

        for (int c = 0; c < D_DIM / KCH; c++, ct++) {
            // Wait for chunk ct (pending groups: ct .. ct+1).
            if (ct == cTotal - 1) {
                asm volatile("cp.async.wait_group 0;\n" ::: "memory");
            } else {
                asm volatile("cp.async.wait_group 1;\n" ::: "memory");
            }
            // Single barrier: publishes chunk ct AND closes reads of the
            // buffer chunk ct+2 will overwrite.
            __syncthreads();

            if (ct + 2 < cTotal) {
                int nct = ct + 2;
                load_chunk_async(sA + (nct % NSTAGE) * SA_WORDS, xq,
                                 (nct >> 2) * QTILE, (nct & 3) * KCH, tid);
            }

            const float* A  = sA + (ct % NSTAGE) * SA_WORDS;
            const float* Bc = sB + c * KCH * SBN_STRIDE;
#pragma unroll 8
            for (int k = 0; k < KCH; k++) {
                const float* Ak = A  + k * SA_STRIDE;
                const float* Bk = Bc + k * SBN_STRIDE;
                // b: warp-uniform 16B load -> broadcast; pairs (n,n+1) land
                // pre-packed in 64-bit lanes.
                ulonglong2 bpair = *(const ulonglong2*)(Bk + ty * 4);
                unsigned long long bp0 = bpair.x, bp1 = bpair.y;
                // a: conflict-free LDS.128 (16B lane stride), duplicate lanes.
                float4 av = *(const float4*)(Ak + tx * 4);
                unsigned long long a0 = dup_f32(av.x);
                unsigned long long a1 = dup_f32(av.y);
                unsigned long long a2 = dup_f32(av.z);
                unsigned long long a3 = dup_f32(av.w);
                acc2[0][0] = ffma2(bp0, a0, acc2[0][0]);
                acc2[1][0] = ffma2(bp1, a0, acc2[1][0]);
                acc2[0][1] = ffma2(bp0, a1, acc2[0][1]);
                acc2[1][1] = ffma2(bp1, a1, acc2[1][1]);
                acc2[0][2] = ffma2(bp0, a2, acc2[0][2]);
                acc2[1][2] = ffma2(bp1, a2, acc2[1][2]);
                acc2[0][3] = ffma2(bp0, a3, acc2[0][3]);
                acc2[1][3] = ffma2(bp1, a3, acc2[1][3]);
            }
        }

        // ---------------- Top-k update (warp-private rows) ----------------
        // Warp ty owns rows n0 + ty*4 .. +3. Pair p: lo -> row ty*4+2p,
        // hi -> row ty*4+2p+1; lane tx holds q = q0 + tx*4 + j.
#pragma unroll
        for (int p = 0; p < 2; p++) {
#pragma unroll
            for (int half = 0; half < 2; half++) {
                int row = ty * 4 + 2 * p + half;
                unsigned th = thresh[row];
                unsigned ov[4];
                bool any = false;
#pragma unroll
                for (int j = 0; j < 4; j++) {
                    unsigned bits = half ? (unsigned)(acc2[p][j] >> 32)
                                         : (unsigned)(acc2[p][j] & 0xFFFFFFFFull);
                    ov[j] = fp32_ord(__uint_as_float(bits));
                    any |= (ov[j] >= th);
                }
                unsigned bal = __ballot_sync(0xffffffffu, any);
                while (bal) {
                    int t = __ffs(bal) - 1;
                    bal &= bal - 1;
                    if (tx == t) {
                        unsigned long long* L = lists + (size_t)row * K_TOP;
#pragma unroll
                        for (int j = 0; j < 4; j++) {
                            unsigned long long key =
                                ((unsigned long long)ov[j] << 32) |
                                (unsigned long long)(0xFFFFFFFFu - (unsigned)(q0 + tx * 4 + j));
                            if (key > L[K_TOP - 1]) {
                                int pp = K_TOP - 1;
                                while (pp > 0 && L[pp - 1] < key) { L[pp] = L[pp - 1]; pp--; }
                                L[pp] = key;
                            }
                        }
                        thresh[row] = (unsigned)(L[K_TOP - 1] >> 32);
                    }
                    __syncwarp();
                }
            }
        }
        // lists/thresh writes close at the next chunk's __syncthreads (or the
        // one below after the last tile).
    }

    __syncthreads();
    // Emit: out[k][n] as FLOAT32 values (0..4095 exactly representable),
    // lists sorted by (value desc, index asc) == lax.top_k order.
    for (int e = tid; e < TILE * K_TOP; e += NTHREADS) {
        int row = e / K_TOP;
        int k   = e % K_TOP;
        unsigned idx = 0xFFFFFFFFu -
            (unsigned)(lists[(size_t)row * K_TOP + k] & 0xFFFFFFFFull);
        out[(size_t)k * N + (n0 + row)] = (float)idx;
    }
}

// ---------------------------------------------------------------------------
// Launch. Inputs bound BY SIZE: N comes from out_size (out is [21, N]); the
// input with N*128 elements is xb (database), the other is xq (queries).
// ---------------------------------------------------------------------------
extern "C" void kernel_launch(void* const* d_in, const int* in_sizes, int n_in,
                              void* d_out, int out_size)
{
    float* out = (float*)d_out;

    const int N = out_size / K_TOP;
    const float* xq;
    const float* xb;
    int Q;

    if (in_sizes[0] == N * D_DIM && in_sizes[1] != N * D_DIM) {
        xb = (const float*)d_in[0];
        xq = (const float*)d_in[1];
        Q  = in_sizes[1] / D_DIM;
    } else {
        xq = (const float*)d_in[0];
        xb = (const float*)d_in[1];
        Q  = in_sizes[0] / D_DIM;
    }

    // Per-CTA smem: sB 128*68*4 = 34.8 KB, ring 3*32*132*4 = 50.7 KB,
    // lists 64*21*8 = 10.8 KB, thresh 0.25 KB  ->  ~96.5 KB; 2 CTAs/SM fit.
    const int smem_bytes = SB_TOT * 4 + NSTAGE * SA_WORDS * 4
                         + TILE * K_TOP * 8 + TILE * 4;
    cudaFuncSetAttribute(fused_gemm_topk_kernel,
                         cudaFuncAttributeMaxDynamicSharedMemorySize, smem_bytes);

    fused_gemm_topk_kernel<<<N / TILE, NTHREADS, smem_bytes>>>(xq, xb, Q, N, out);
}